// round 8
// baseline (speedup 1.0000x reference)
#include <cuda_runtime.h>
#include <math.h>

#define M_ROWS 512
#define K_COMP 8
#define B_PTS  4096
#define PHI_DIM 120
#define Z_COLS 80
#define LOG2PI_F 1.8378770664093453f
#define LOG2E_F  1.4426950408889634f

#define NBLK   296        // 148 SMs x 2 CTAs of 256 threads (16 warps/SM)
#define NCHUNK 4          // chunks per m, 1024 points each
#define NTICK  (M_ROWS * NCHUNK)

// Scratch (device globals — no allocation allowed)
// per (m,k) 16 floats: [A00,A10,A11,A20][A21,A22,A30,A31][A32,A33,B0,B1][B2,B3,NCK,pad]
__device__ float g_par[M_ROWS][128];
__device__ float g_zT[72][M_ROWS];                // z cols 0..71, column-major
__device__ float g_respP[NCHUNK][K_COMP][M_ROWS]; // per-chunk resp partials
__device__ unsigned g_ticket, g_arrive1, g_arrive2, g_done;

__device__ __forceinline__ float ex2f(float x) {
    float r; asm("ex2.approx.f32 %0, %1;" : "=f"(r) : "f"(x)); return r;
}
__device__ __forceinline__ float rcpf(float x) {
    float r; asm("rcp.approx.f32 %0, %1;" : "=f"(r) : "f"(x)); return r;
}

__device__ __forceinline__ void grid_barrier(unsigned* ctr) {
    __syncthreads();
    if (threadIdx.x == 0) {
        __threadfence();
        atomicAdd(ctr, 1u);
        volatile unsigned* p = ctr;
        while (*p < NBLK) __nanosleep(64);
    }
    __syncthreads();
    __threadfence();
}

// ---------------------------------------------------------------------------
__global__ void __launch_bounds__(256, 2) gmm_all(const float* __restrict__ phi,
                                                  const float4* __restrict__ X,
                                                  float* __restrict__ out) {
    const int tid = threadIdx.x;
    const unsigned lane = tid & 31;
    const unsigned wid = tid >> 5;

    __shared__ float4 spar[32];          // 8 k x 4 float4
    __shared__ float sred[8][K_COMP];
    __shared__ unsigned s_item;

    // ===================== PHASE 0: prep (4096 (m,k) tasks) =================
    {
        int gid = blockIdx.x * 256 + tid;
        if (gid < M_ROWS * K_COMP) {
            const int m = gid >> 3, k = gid & 7;
            const float* pm = phi + m * PHI_DIM;

            float mx = -INFINITY;
            #pragma unroll
            for (int j = 0; j < K_COMP; j++) mx = fmaxf(mx, pm[j]);
            float s = 0.f;
            #pragma unroll
            for (int j = 0; j < K_COMP; j++) s += __expf(pm[j] - mx);
            float pik = __expf(pm[k] - mx) / s;

            float mu0 = pm[8 + k * 4 + 0];
            float mu1 = pm[8 + k * 4 + 1];
            float mu2 = pm[8 + k * 4 + 2];
            float mu3 = pm[8 + k * 4 + 3];

            const float* lv = pm + 40 + k * 10;
            float L00 = lv[0], L10 = lv[1], L11 = lv[2], L20 = lv[3], L21 = lv[4];
            float L22 = lv[5], L30 = lv[6], L31 = lv[7], L32 = lv[8], L33 = lv[9];

            float G00 = 1.0f / L00, G11 = 1.0f / L11, G22 = 1.0f / L22, G33 = 1.0f / L33;
            float G10 = -L10 * G00 * G11;
            float G21 = -L21 * G11 * G22;
            float G20 = -(L20 * G00 + L21 * G10) * G22;
            float G32 = -L32 * G22 * G33;
            float G31 = -(L31 * G11 + L32 * G21) * G33;
            float G30 = -(L30 * G00 + L31 * G10 + L32 * G20) * G33;

            const float sc = sqrtf(0.5f * LOG2E_F);
            float A00 = sc * G00, A10 = sc * G10, A11 = sc * G11;
            float A20 = sc * G20, A21 = sc * G21, A22 = sc * G22;
            float A30 = sc * G30, A31 = sc * G31, A32 = sc * G32, A33 = sc * G33;

            float B0 = -(A00 * mu0);
            float B1 = -(A10 * mu0 + A11 * mu1);
            float B2 = -(A20 * mu0 + A21 * mu1 + A22 * mu2);
            float B3 = -(A30 * mu0 + A31 * mu1 + A32 * mu2 + A33 * mu3);

            float log_det = 2.0f * (__logf(fmaxf(fabsf(L00), 1e-8f)) +
                                    __logf(fmaxf(fabsf(L11), 1e-8f)) +
                                    __logf(fmaxf(fabsf(L22), 1e-8f)) +
                                    __logf(fmaxf(fabsf(L33), 1e-8f)));
            float ckv = __logf(fmaxf(pik, 1e-8f)) - 0.5f * (4.0f * LOG2PI_F + log_det);

            float* P = g_par[m] + k * 16;
            P[0] = A00; P[1] = A10; P[2] = A11; P[3] = A20;
            P[4] = A21; P[5] = A22; P[6] = A30; P[7] = A31;
            P[8] = A32; P[9] = A33; P[10] = B0; P[11] = B1;
            P[12] = B2; P[13] = B3; P[14] = -(ckv * LOG2E_F); P[15] = 0.f;

            g_zT[k * 4 + 0][m] = mu0;
            g_zT[k * 4 + 1][m] = mu1;
            g_zT[k * 4 + 2][m] = mu2;
            g_zT[k * 4 + 3][m] = mu3;
            g_zT[32 + k * 4 + 0][m] = __logf(fmaxf(fabsf(L00), 1e-6f));
            g_zT[32 + k * 4 + 1][m] = __logf(fmaxf(fabsf(L11), 1e-6f));
            g_zT[32 + k * 4 + 2][m] = __logf(fmaxf(fabsf(L22), 1e-6f));
            g_zT[32 + k * 4 + 3][m] = __logf(fmaxf(fabsf(L33), 1e-6f));
            g_zT[64 + k][m] = pik;
        }
    }

    grid_barrier(&g_arrive1);

    // ===================== PHASE 1: block-ticketed main loop =================
    for (;;) {
        if (tid == 0) s_item = atomicAdd(&g_ticket, 1u);
        __syncthreads();
        const unsigned item = s_item;
        if (item >= NTICK) break;
        const int m = item >> 2;
        const int ch = item & (NCHUNK - 1);

        if (tid < 32) spar[tid] = ((const float4*)g_par[m])[tid];
        __syncthreads();

        // 4 points per thread
        float4 x[4];
        #pragma unroll
        for (int j = 0; j < 4; j++) x[j] = X[ch * 1024 + tid + 256 * j];

        // q[k][j] = |A x + b|^2 - ck2  (log2 units, = -lj)
        float q[K_COMP][4];
        #pragma unroll
        for (int k = 0; k < K_COMP; k++) {
            float4 p0 = spar[k * 4 + 0];
            float4 p1 = spar[k * 4 + 1];
            float4 p2 = spar[k * 4 + 2];
            float4 p3 = spar[k * 4 + 3];
            #pragma unroll
            for (int j = 0; j < 4; j++) {
                float a0 = __fmaf_rn(x[j].x, p0.x, p2.z);
                float a1 = __fmaf_rn(x[j].x, p0.y, __fmaf_rn(x[j].y, p0.z, p2.w));
                float a2 = __fmaf_rn(x[j].x, p0.w,
                           __fmaf_rn(x[j].y, p1.x, __fmaf_rn(x[j].z, p1.y, p3.x)));
                float a3 = __fmaf_rn(x[j].x, p1.z,
                           __fmaf_rn(x[j].y, p1.w,
                           __fmaf_rn(x[j].z, p2.x, __fmaf_rn(x[j].w, p2.y, p3.y))));
                q[k][j] = __fmaf_rn(a0, a0,
                          __fmaf_rn(a1, a1,
                          __fmaf_rn(a2, a2, __fmaf_rn(a3, a3, p3.z))));
            }
        }

        // softmax over k per point: min(q) shift, e = ex2(mn - q) (arg <= 0)
        float mn[4];
        #pragma unroll
        for (int j = 0; j < 4; j++) {
            float v = fminf(fminf(fminf(q[0][j], q[1][j]), fminf(q[2][j], q[3][j])),
                            fminf(fminf(q[4][j], q[5][j]), fminf(q[6][j], q[7][j])));
            mn[j] = v;
        }
        #pragma unroll
        for (int k = 0; k < K_COMP; k++)
            #pragma unroll
            for (int j = 0; j < 4; j++)
                q[k][j] = ex2f(mn[j] - q[k][j]);   // e overwrites q

        float inv[4];
        #pragma unroll
        for (int j = 0; j < 4; j++) {
            float s = ((q[0][j] + q[1][j]) + (q[2][j] + q[3][j])) +
                      ((q[4][j] + q[5][j]) + (q[6][j] + q[7][j]));
            inv[j] = rcpf(s);                      // s >= 1, safe
        }

        float acc[K_COMP];
        #pragma unroll
        for (int k = 0; k < K_COMP; k++) {
            float a = q[k][0] * inv[0];
            a = __fmaf_rn(q[k][1], inv[1], a);
            a = __fmaf_rn(q[k][2], inv[2], a);
            a = __fmaf_rn(q[k][3], inv[3], a);
            acc[k] = a;
        }

        // block reduce (8 warps)
        #pragma unroll
        for (int k = 0; k < K_COMP; k++) {
            float v = acc[k];
            v += __shfl_down_sync(0xffffffffu, v, 16);
            v += __shfl_down_sync(0xffffffffu, v, 8);
            v += __shfl_down_sync(0xffffffffu, v, 4);
            v += __shfl_down_sync(0xffffffffu, v, 2);
            v += __shfl_down_sync(0xffffffffu, v, 1);
            if (lane == 0) sred[wid][k] = v;
        }
        __syncthreads();
        if (tid < K_COMP) {
            float v = ((sred[0][tid] + sred[1][tid]) + (sred[2][tid] + sred[3][tid])) +
                      ((sred[4][tid] + sred[5][tid]) + (sred[6][tid] + sred[7][tid]));
            g_respP[ch][tid][m] = v;
        }
        __syncthreads();
    }

    grid_barrier(&g_arrive2);

    // ===================== PHASE 2: standardization (blocks 0..79) ===========
    if (blockIdx.x < Z_COLS) {
        const int c = blockIdx.x;
        float v[2];
        if (c < 72) {
            const float* col = g_zT[c];
            #pragma unroll
            for (int j = 0; j < 2; j++) v[j] = col[tid + 256 * j];
        } else {
            const int k = c - 72;
            #pragma unroll
            for (int j = 0; j < 2; j++) {
                int r = tid + 256 * j;
                v[j] = (g_respP[0][k][r] + g_respP[1][k][r] +
                        g_respP[2][k][r] + g_respP[3][k][r]) * (1.0f / (float)B_PTS);
            }
        }

        __shared__ float nsh[8];
        __shared__ float n_mean, n_rstd;

        float s = v[0] + v[1];
        s += __shfl_down_sync(0xffffffffu, s, 16);
        s += __shfl_down_sync(0xffffffffu, s, 8);
        s += __shfl_down_sync(0xffffffffu, s, 4);
        s += __shfl_down_sync(0xffffffffu, s, 2);
        s += __shfl_down_sync(0xffffffffu, s, 1);
        if (lane == 0) nsh[wid] = s;
        __syncthreads();
        if (tid == 0) {
            float t = ((nsh[0] + nsh[1]) + (nsh[2] + nsh[3])) +
                      ((nsh[4] + nsh[5]) + (nsh[6] + nsh[7]));
            n_mean = t * (1.0f / (float)M_ROWS);
        }
        __syncthreads();
        float mean = n_mean;

        float qsum = 0.f;
        #pragma unroll
        for (int j = 0; j < 2; j++) {
            v[j] -= mean;
            qsum = __fmaf_rn(v[j], v[j], qsum);
        }
        qsum += __shfl_down_sync(0xffffffffu, qsum, 16);
        qsum += __shfl_down_sync(0xffffffffu, qsum, 8);
        qsum += __shfl_down_sync(0xffffffffu, qsum, 4);
        qsum += __shfl_down_sync(0xffffffffu, qsum, 2);
        qsum += __shfl_down_sync(0xffffffffu, qsum, 1);
        __syncthreads();
        if (lane == 0) nsh[wid] = qsum;
        __syncthreads();
        if (tid == 0) {
            float t = ((nsh[0] + nsh[1]) + (nsh[2] + nsh[3])) +
                      ((nsh[4] + nsh[5]) + (nsh[6] + nsh[7]));
            float var = t * (1.0f / (float)(M_ROWS - 1));
            n_rstd = 1.0f / fmaxf(sqrtf(var), 1e-6f);
        }
        __syncthreads();
        float rstd = n_rstd;
        #pragma unroll
        for (int j = 0; j < 2; j++) {
            int r = tid + 256 * j;
            out[r * Z_COLS + c] = v[j] * rstd;
        }
    }

    // ============== counter reset (state -> 0 for graph replay) ==============
    __syncthreads();
    if (tid == 0) {
        __threadfence();
        unsigned d = atomicAdd(&g_done, 1u);
        if (d == NBLK - 1) {
            g_ticket = 0u;
            g_arrive1 = 0u;
            g_arrive2 = 0u;
            g_done = 0u;
            __threadfence();
        }
    }
}

// ---------------------------------------------------------------------------
extern "C" void kernel_launch(void* const* d_in, const int* in_sizes, int n_in,
                              void* d_out, int out_size) {
    const float* phi = (const float*)d_in[0];
    const float4* X = (const float4*)d_in[1];
    float* out = (float*)d_out;

    gmm_all<<<NBLK, 256>>>(phi, X, out);
}